// round 1
// baseline (speedup 1.0000x reference)
#include <cuda_runtime.h>
#include <math.h>

#define NB 8
#define CD 128
#define KC 64
#define HD 16
#define WD 900
#define HW 14400      // HD*WD
#define NCH 90        // chunks of 10 along W
#define NW 30         // windows
#define NR 240        // NB*NW rows of vlad
#define OD 256
#define KSP 16        // K-split for final GEMM

__device__ float g_a[(size_t)NB * HW * KC];          // (n,q,k) softmax assignments
__device__ float g_xt[(size_t)NB * HW * CD];         // (n,q,c) transposed x
__device__ float g_cwx[(size_t)NB * NCH * KC * CD];  // (n,j,k,c) chunk weighted sums
__device__ float g_ca[(size_t)NB * NCH * KC];        // (n,j,k) chunk a-sums
__device__ float g_vlad[(size_t)NR * KC * CD];       // normalized vlad rows
__device__ float g_part[(size_t)KSP * NR * OD];      // split-K partials

// ---------------------------------------------------------------------------
// Kernel A: logits GEMM + softmax over k -> g_a (n,q,k); also writes x
// transposed to g_xt (n,q,c). One block = 128 positions of one n.
// ---------------------------------------------------------------------------
__global__ __launch_bounds__(256) void kA(const float* __restrict__ x,
                                          const float* __restrict__ cw,
                                          const float* __restrict__ cb) {
    __shared__ float ws[32][64];    // [c_local][k]
    __shared__ float xs[32][128];   // [c_local][p]
    __shared__ float red[8][128];   // softmax cross-warp reduction

    const int tid  = threadIdx.x;
    const int bx   = blockIdx.x;
    const int n    = bx / 113;
    const int q0   = (bx % 113) * 128;
    const int tcol = tid & 31;      // p group: p = tcol*4 + j
    const int trow = tid >> 5;      // k group: k = trow*8 + i

    float acc[8][4];
#pragma unroll
    for (int i = 0; i < 8; i++)
#pragma unroll
        for (int j = 0; j < 4; j++) acc[i][j] = 0.f;

    const float* xb  = x + (size_t)n * CD * HW;
    float*       xtb = g_xt + (size_t)n * HW * CD;

    for (int c0 = 0; c0 < CD; c0 += 32) {
        // conv_w chunk, transposed: ws[c][k]
        for (int i = tid; i < 2048; i += 256) {
            int k = i & 63, c = i >> 6;
            ws[c][k] = cw[k * CD + c0 + c];
        }
        // x chunk: xs[c][p]
        {
            int p  = (tid & 31) * 4;
            int r0 = tid >> 5;
#pragma unroll
            for (int rr = 0; rr < 4; rr++) {
                int c = r0 + rr * 8;
                float4 v;
                if (q0 + p < HW)
                    v = *(const float4*)(xb + (size_t)(c0 + c) * HW + q0 + p);
                else
                    v = make_float4(0.f, 0.f, 0.f, 0.f);
                *(float4*)&xs[c][p] = v;
            }
        }
        __syncthreads();
#pragma unroll
        for (int c = 0; c < 32; c++) {
            float4 xv = *(float4*)&xs[c][tcol * 4];
            float4 w0 = *(float4*)&ws[c][trow * 8];
            float4 w1 = *(float4*)&ws[c][trow * 8 + 4];
            float xr[4] = {xv.x, xv.y, xv.z, xv.w};
            float wr[8] = {w0.x, w0.y, w0.z, w0.w, w1.x, w1.y, w1.z, w1.w};
#pragma unroll
            for (int i = 0; i < 8; i++)
#pragma unroll
                for (int j = 0; j < 4; j++) acc[i][j] += wr[i] * xr[j];
        }
        // write transposed x from the smem tile
#pragma unroll
        for (int pass = 0; pass < 4; pass++) {
            int idx = tid + pass * 256;
            int q   = idx & 127;
            int c4  = idx >> 7;   // 0..7
            if (q0 + q < HW) {
                float4 v = make_float4(xs[c4 * 4 + 0][q], xs[c4 * 4 + 1][q],
                                       xs[c4 * 4 + 2][q], xs[c4 * 4 + 3][q]);
                *(float4*)&xtb[(size_t)(q0 + q) * CD + c0 + c4 * 4] = v;
            }
        }
        __syncthreads();
    }

    // add bias
#pragma unroll
    for (int i = 0; i < 8; i++) {
        float bb = cb[trow * 8 + i];
#pragma unroll
        for (int j = 0; j < 4; j++) acc[i][j] += bb;
    }

    // softmax over k (64 values spread as 8 regs x 8 warps)
    float m4[4];
#pragma unroll
    for (int j = 0; j < 4; j++) {
        float lm = acc[0][j];
#pragma unroll
        for (int i = 1; i < 8; i++) lm = fmaxf(lm, acc[i][j]);
        red[trow][tcol * 4 + j] = lm;
    }
    __syncthreads();
#pragma unroll
    for (int j = 0; j < 4; j++) {
        float mm = red[0][tcol * 4 + j];
#pragma unroll
        for (int r = 1; r < 8; r++) mm = fmaxf(mm, red[r][tcol * 4 + j]);
        m4[j] = mm;
    }
    __syncthreads();
    float ls[4] = {0.f, 0.f, 0.f, 0.f};
#pragma unroll
    for (int i = 0; i < 8; i++)
#pragma unroll
        for (int j = 0; j < 4; j++) {
            acc[i][j] = __expf(acc[i][j] - m4[j]);
            ls[j] += acc[i][j];
        }
#pragma unroll
    for (int j = 0; j < 4; j++) red[trow][tcol * 4 + j] = ls[j];
    __syncthreads();
#pragma unroll
    for (int j = 0; j < 4; j++) {
        float s = 0.f;
#pragma unroll
        for (int r = 0; r < 8; r++) s += red[r][tcol * 4 + j];
        ls[j] = 1.0f / s;
    }

    float* ab = g_a + (size_t)n * HW * KC;
#pragma unroll
    for (int j = 0; j < 4; j++) {
        int q = q0 + tcol * 4 + j;
        if (q < HW) {
            float4 v0 = make_float4(acc[0][j] * ls[j], acc[1][j] * ls[j],
                                    acc[2][j] * ls[j], acc[3][j] * ls[j]);
            float4 v1 = make_float4(acc[4][j] * ls[j], acc[5][j] * ls[j],
                                    acc[6][j] * ls[j], acc[7][j] * ls[j]);
            *(float4*)&ab[(size_t)q * KC + trow * 8]     = v0;
            *(float4*)&ab[(size_t)q * KC + trow * 8 + 4] = v1;
        }
    }
}

// ---------------------------------------------------------------------------
// Kernel B: per (n, chunk j): WXc[k,c] = sum over 160 positions a[q,k]*x[q,c];
// also Ac[k] = sum a. 720 blocks.
// ---------------------------------------------------------------------------
__global__ __launch_bounds__(256) void kB() {
    __shared__ float asm_[16][64];   // [p_local][k]
    __shared__ float xsm[16][128];   // [p_local][c]
    __shared__ float redA[16][64];

    const int tid  = threadIdx.x;
    const int bx   = blockIdx.x;
    const int n    = bx / NCH;
    const int j    = bx % NCH;
    const int tcol = tid & 31;      // c = tcol*4 + jj
    const int trow = tid >> 5;      // k = trow*8 + i

    const int arow = tid >> 4;          // 0..15
    const int ak4  = (tid & 15) * 4;    // k offset for a loads
    const int xc4  = (tid & 31) * 4;    // c offset for x loads
    const int xrow = tid >> 5;          // 0..7

    float acc[8][4];
#pragma unroll
    for (int i = 0; i < 8; i++)
#pragma unroll
        for (int jj = 0; jj < 4; jj++) acc[i][jj] = 0.f;
    float4 asum = make_float4(0.f, 0.f, 0.f, 0.f);

    const float* ab = g_a + (size_t)n * HW * KC;
    const float* xb = g_xt + (size_t)n * HW * CD;

    for (int step = 0; step < 10; step++) {
        {
            int p = step * 16 + arow;
            int q = (p / 10) * WD + j * 10 + (p % 10);
            float4 v = *(const float4*)(ab + (size_t)q * KC + ak4);
            *(float4*)&asm_[arow][ak4] = v;
            asum.x += v.x; asum.y += v.y; asum.z += v.z; asum.w += v.w;
        }
#pragma unroll
        for (int rr = 0; rr < 2; rr++) {
            int p = step * 16 + xrow + rr * 8;
            int q = (p / 10) * WD + j * 10 + (p % 10);
            *(float4*)&xsm[xrow + rr * 8][xc4] =
                *(const float4*)(xb + (size_t)q * CD + xc4);
        }
        __syncthreads();
#pragma unroll
        for (int pp = 0; pp < 16; pp++) {
            float4 a0 = *(float4*)&asm_[pp][trow * 8];
            float4 a1 = *(float4*)&asm_[pp][trow * 8 + 4];
            float4 xv = *(float4*)&xsm[pp][tcol * 4];
            float xr[4] = {xv.x, xv.y, xv.z, xv.w};
            float wr[8] = {a0.x, a0.y, a0.z, a0.w, a1.x, a1.y, a1.z, a1.w};
#pragma unroll
            for (int i = 0; i < 8; i++)
#pragma unroll
                for (int jj = 0; jj < 4; jj++) acc[i][jj] += wr[i] * xr[jj];
        }
        __syncthreads();
    }

    // reduce a-sums over the 16 row-threads
    *(float4*)&redA[arow][ak4] = asum;
    __syncthreads();
    if (tid < 64) {
        float s = 0.f;
#pragma unroll
        for (int r = 0; r < 16; r++) s += redA[r][tid];
        g_ca[((size_t)n * NCH + j) * KC + tid] = s;
    }

    float* ob = g_cwx + (size_t)(n * NCH + j) * KC * CD;
#pragma unroll
    for (int i = 0; i < 8; i++) {
        float4 v = make_float4(acc[i][0], acc[i][1], acc[i][2], acc[i][3]);
        *(float4*)&ob[(size_t)(trow * 8 + i) * CD + tcol * 4] = v;
    }
}

// ---------------------------------------------------------------------------
// Kernel C1: window assembly + residual + intra/global L2 norms -> g_vlad
// One block per (n,t) window. 240 blocks.
// ---------------------------------------------------------------------------
__global__ __launch_bounds__(256) void kC1(const float* __restrict__ centers) {
    __shared__ float Asm[64];
    __shared__ float gred[8];

    const int wi   = blockIdx.x;
    const int n    = wi / NW;
    const int t    = wi % NW;
    const int tid  = threadIdx.x;
    const int tcol = tid & 31;
    const int trow = tid >> 5;

    if (tid < 64) {
        float s = 0.f;
#pragma unroll
        for (int i = 0; i < 20; i++) {
            int jj = (3 * t + i + 80) % NCH;
            s += g_ca[((size_t)n * NCH + jj) * KC + tid];
        }
        Asm[tid] = s;
    }
    __syncthreads();

    float acc[8][4];
#pragma unroll
    for (int i = 0; i < 8; i++)
#pragma unroll
        for (int jj = 0; jj < 4; jj++) acc[i][jj] = 0.f;

    for (int i = 0; i < 20; i++) {
        int jj = (3 * t + i + 80) % NCH;
        const float* base = g_cwx + (size_t)(n * NCH + jj) * KC * CD;
#pragma unroll
        for (int r = 0; r < 8; r++) {
            float4 v = *(const float4*)&base[(size_t)(trow * 8 + r) * CD + tcol * 4];
            acc[r][0] += v.x; acc[r][1] += v.y; acc[r][2] += v.z; acc[r][3] += v.w;
        }
    }

    float vv[8][4];
    float vsq = 0.f;
#pragma unroll
    for (int r = 0; r < 8; r++) {
        float As   = Asm[trow * 8 + r];
        float4 cen = *(const float4*)&centers[(size_t)(trow * 8 + r) * CD + tcol * 4];
        float r0 = acc[r][0] - cen.x * As;
        float r1 = acc[r][1] - cen.y * As;
        float r2 = acc[r][2] - cen.z * As;
        float r3 = acc[r][3] - cen.w * As;
        float ns = r0 * r0 + r1 * r1 + r2 * r2 + r3 * r3;
#pragma unroll
        for (int off = 16; off > 0; off >>= 1)
            ns += __shfl_xor_sync(0xffffffffu, ns, off);
        float inv = 1.0f / fmaxf(sqrtf(ns), 1e-12f);
        vv[r][0] = r0 * inv; vv[r][1] = r1 * inv;
        vv[r][2] = r2 * inv; vv[r][3] = r3 * inv;
        vsq += vv[r][0] * vv[r][0] + vv[r][1] * vv[r][1] +
               vv[r][2] * vv[r][2] + vv[r][3] * vv[r][3];
    }
#pragma unroll
    for (int off = 16; off > 0; off >>= 1)
        vsq += __shfl_xor_sync(0xffffffffu, vsq, off);
    if (tcol == 0) gred[trow] = vsq;
    __syncthreads();
    float g = 0.f;
#pragma unroll
    for (int r = 0; r < 8; r++) g += gred[r];
    float ginv = 1.0f / fmaxf(sqrtf(g), 1e-12f);

    float* outb = g_vlad + (size_t)wi * KC * CD;
#pragma unroll
    for (int r = 0; r < 8; r++) {
        float4 v = make_float4(vv[r][0] * ginv, vv[r][1] * ginv,
                               vv[r][2] * ginv, vv[r][3] * ginv);
        *(float4*)&outb[(size_t)(trow * 8 + r) * CD + tcol * 4] = v;
    }
}

// ---------------------------------------------------------------------------
// Kernel C2: split-K GEMM partials: (240 x 8192) @ mlp_w^T(8192 x 256)
// BM=48, BN=64, Ksplit=16 (chunk 512). grid (5,4,16).
// ---------------------------------------------------------------------------
__global__ __launch_bounds__(256, 2) void kC2(const float* __restrict__ mw) {
    __shared__ float As[32][49];
    __shared__ float Bs[32][68];

    const int m0  = blockIdx.x * 48;
    const int n0  = blockIdx.y * 64;
    const int k0  = blockIdx.z * 512;
    const int tid = threadIdx.x;
    const int tm  = tid & 15;    // m = tm*3 + i
    const int tn  = tid >> 4;    // n = tn*4 + j

    float acc[3][4];
#pragma unroll
    for (int i = 0; i < 3; i++)
#pragma unroll
        for (int jj = 0; jj < 4; jj++) acc[i][jj] = 0.f;

    const int kk = tid & 31;
    const int r  = tid >> 5;   // 0..7

    for (int ks = 0; ks < 16; ks++) {
        int kb = k0 + ks * 32;
#pragma unroll
        for (int pass = 0; pass < 6; pass++) {
            int m = r + pass * 8;
            As[kk][m] = g_vlad[(size_t)(m0 + m) * 8192 + kb + kk];
        }
#pragma unroll
        for (int pass = 0; pass < 8; pass++) {
            int nn = r + pass * 8;
            Bs[kk][nn] = mw[(size_t)(n0 + nn) * 8192 + kb + kk];
        }
        __syncthreads();
#pragma unroll
        for (int kki = 0; kki < 32; kki++) {
            float a0 = As[kki][tm * 3 + 0];
            float a1 = As[kki][tm * 3 + 1];
            float a2 = As[kki][tm * 3 + 2];
            float4 b = *(float4*)&Bs[kki][tn * 4];
            acc[0][0] += a0 * b.x; acc[0][1] += a0 * b.y; acc[0][2] += a0 * b.z; acc[0][3] += a0 * b.w;
            acc[1][0] += a1 * b.x; acc[1][1] += a1 * b.y; acc[1][2] += a1 * b.z; acc[1][3] += a1 * b.w;
            acc[2][0] += a2 * b.x; acc[2][1] += a2 * b.y; acc[2][2] += a2 * b.z; acc[2][3] += a2 * b.w;
        }
        __syncthreads();
    }

    float* pb = g_part + (size_t)blockIdx.z * NR * OD;
#pragma unroll
    for (int i = 0; i < 3; i++) {
        float4 v = make_float4(acc[i][0], acc[i][1], acc[i][2], acc[i][3]);
        *(float4*)&pb[(size_t)(m0 + tm * 3 + i) * OD + n0 + tn * 4] = v;
    }
}

// ---------------------------------------------------------------------------
// Kernel C3: reduce split-K partials + bias + final row L2 norm -> output
// ---------------------------------------------------------------------------
__global__ __launch_bounds__(256) void kC3(const float* __restrict__ mb,
                                           float* __restrict__ out) {
    __shared__ float red[8];
    const int rrow = blockIdx.x;
    const int tid  = threadIdx.x;
    float s = mb[tid];
#pragma unroll
    for (int ks = 0; ks < KSP; ks++)
        s += g_part[((size_t)ks * NR + rrow) * OD + tid];
    float sq = s * s;
#pragma unroll
    for (int off = 16; off > 0; off >>= 1)
        sq += __shfl_xor_sync(0xffffffffu, sq, off);
    if ((tid & 31) == 0) red[tid >> 5] = sq;
    __syncthreads();
    float tot = 0.f;
#pragma unroll
    for (int i = 0; i < 8; i++) tot += red[i];
    out[(size_t)rrow * OD + tid] = s / fmaxf(sqrtf(tot), 1e-12f);
}

extern "C" void kernel_launch(void* const* d_in, const int* in_sizes, int n_in,
                              void* d_out, int out_size) {
    (void)in_sizes; (void)n_in; (void)out_size;
    const float* x       = (const float*)d_in[0];
    const float* centers = (const float*)d_in[1];
    const float* cw      = (const float*)d_in[2];
    const float* cb      = (const float*)d_in[3];
    const float* mw      = (const float*)d_in[4];
    const float* mb      = (const float*)d_in[5];
    float* out = (float*)d_out;

    kA<<<NB * 113, 256>>>(x, cw, cb);
    kB<<<NB * NCH, 256>>>();
    kC1<<<NR, 256>>>(centers);
    kC2<<<dim3(5, 4, KSP), 256>>>(mw);
    kC3<<<NR, 256>>>(mb, out);
}

// round 3
// speedup vs baseline: 1.2249x; 1.2249x over previous
#include <cuda_runtime.h>
#include <cuda_bf16.h>
#include <math.h>
#include <stdint.h>

#define NB 8
#define CD 128
#define KC 64
#define HD 16
#define WD 900
#define HW 14400      // HD*WD
#define NCH 90        // chunks of 10 along W
#define NW 30         // windows
#define NR 240        // NB*NW rows of vlad
#define NRP 256       // padded rows for mma
#define OD 256
#define KSP 16        // K-split for final GEMM
#define KD 8192       // KC*CD

__device__ unsigned short g_a_hi[(size_t)NB * KC * HW];   // bf16 bits, (n,k,q)
__device__ unsigned short g_a_lo[(size_t)NB * KC * HW];
__device__ float g_cwx[(size_t)NB * NCH * KC * CD];       // (n,j,k,c)
__device__ float g_ca[(size_t)NB * NCH * KC];             // (n,j,k)
__device__ unsigned short g_vh[(size_t)NRP * KD];         // vlad bf16 hi (rows>=240 stay 0)
__device__ unsigned short g_vl[(size_t)NRP * KD];
__device__ unsigned short g_wh[(size_t)OD * KD];          // mlp_w bf16 hi
__device__ unsigned short g_wl[(size_t)OD * KD];
__device__ float g_part[(size_t)KSP * NR * OD];           // split-K partials

// ---------------------------------------------------------------------------
// helpers
// ---------------------------------------------------------------------------
__device__ __forceinline__ uint32_t smem_u32(const void* p) {
    uint32_t a;
    asm("{ .reg .u64 t; cvta.to.shared.u64 t, %1; cvt.u32.u64 %0, t; }"
        : "=r"(a) : "l"(p));
    return a;
}
__device__ __forceinline__ void ldm_x4(uint32_t (&r)[4], uint32_t addr) {
    asm volatile("ldmatrix.sync.aligned.m8n8.x4.shared.b16 {%0,%1,%2,%3}, [%4];"
                 : "=r"(r[0]), "=r"(r[1]), "=r"(r[2]), "=r"(r[3]) : "r"(addr));
}
__device__ __forceinline__ void mma16816(float (&d)[4], const uint32_t (&a)[4],
                                         const uint32_t b0, const uint32_t b1) {
    asm volatile(
        "mma.sync.aligned.m16n8k16.row.col.f32.bf16.bf16.f32 "
        "{%0,%1,%2,%3}, {%4,%5,%6,%7}, {%8,%9}, {%0,%1,%2,%3};"
        : "+f"(d[0]), "+f"(d[1]), "+f"(d[2]), "+f"(d[3])
        : "r"(a[0]), "r"(a[1]), "r"(a[2]), "r"(a[3]), "r"(b0), "r"(b1));
}
__device__ __forceinline__ void bsplit(float v, unsigned short& h, unsigned short& l) {
    __nv_bfloat16 bh = __float2bfloat16(v);
    __nv_bfloat16 bl = __float2bfloat16(v - __bfloat162float(bh));
    h = __bfloat16_as_ushort(bh);
    l = __bfloat16_as_ushort(bl);
}

// ---------------------------------------------------------------------------
// Kernel W: convert mlp_w to bf16 hi/lo (row-major (od, 8192))
// ---------------------------------------------------------------------------
__global__ __launch_bounds__(256) void kW(const float* __restrict__ mw) {
    size_t base = ((size_t)blockIdx.x * 256 + threadIdx.x) * 8;
    float4 v0 = *(const float4*)(mw + base);
    float4 v1 = *(const float4*)(mw + base + 4);
    float vv[8] = {v0.x, v0.y, v0.z, v0.w, v1.x, v1.y, v1.z, v1.w};
    unsigned short h[8], l[8];
#pragma unroll
    for (int i = 0; i < 8; i++) bsplit(vv[i], h[i], l[i]);
    *(ushort4*)(g_wh + base)     = make_ushort4(h[0], h[1], h[2], h[3]);
    *(ushort4*)(g_wh + base + 4) = make_ushort4(h[4], h[5], h[6], h[7]);
    *(ushort4*)(g_wl + base)     = make_ushort4(l[0], l[1], l[2], l[3]);
    *(ushort4*)(g_wl + base + 4) = make_ushort4(l[4], l[5], l[6], l[7]);
}

// ---------------------------------------------------------------------------
// Kernel A: logits GEMM + softmax over k -> g_a_hi/lo in (n,k,q) bf16 layout.
// ---------------------------------------------------------------------------
__global__ __launch_bounds__(256) void kA(const float* __restrict__ x,
                                          const float* __restrict__ cw,
                                          const float* __restrict__ cb) {
    __shared__ float ws[32][64];
    __shared__ float xs[32][128];
    __shared__ float red[8][128];

    const int tid  = threadIdx.x;
    const int bx   = blockIdx.x;
    const int n    = bx / 113;
    const int q0   = (bx % 113) * 128;
    const int tcol = tid & 31;
    const int trow = tid >> 5;

    float acc[8][4];
#pragma unroll
    for (int i = 0; i < 8; i++)
#pragma unroll
        for (int j = 0; j < 4; j++) acc[i][j] = 0.f;

    const float* xb = x + (size_t)n * CD * HW;

    for (int c0 = 0; c0 < CD; c0 += 32) {
        for (int i = tid; i < 2048; i += 256) {
            int k = i & 63, c = i >> 6;
            ws[c][k] = cw[k * CD + c0 + c];
        }
        {
            int p  = (tid & 31) * 4;
            int r0 = tid >> 5;
#pragma unroll
            for (int rr = 0; rr < 4; rr++) {
                int c = r0 + rr * 8;
                float4 v;
                if (q0 + p < HW)
                    v = *(const float4*)(xb + (size_t)(c0 + c) * HW + q0 + p);
                else
                    v = make_float4(0.f, 0.f, 0.f, 0.f);
                *(float4*)&xs[c][p] = v;
            }
        }
        __syncthreads();
#pragma unroll
        for (int c = 0; c < 32; c++) {
            float4 xv = *(float4*)&xs[c][tcol * 4];
            float4 w0 = *(float4*)&ws[c][trow * 8];
            float4 w1 = *(float4*)&ws[c][trow * 8 + 4];
            float xr[4] = {xv.x, xv.y, xv.z, xv.w};
            float wr[8] = {w0.x, w0.y, w0.z, w0.w, w1.x, w1.y, w1.z, w1.w};
#pragma unroll
            for (int i = 0; i < 8; i++)
#pragma unroll
                for (int j = 0; j < 4; j++) acc[i][j] += wr[i] * xr[j];
        }
        __syncthreads();
    }

#pragma unroll
    for (int i = 0; i < 8; i++) {
        float bb = cb[trow * 8 + i];
#pragma unroll
        for (int j = 0; j < 4; j++) acc[i][j] += bb;
    }

    float m4[4];
#pragma unroll
    for (int j = 0; j < 4; j++) {
        float lm = acc[0][j];
#pragma unroll
        for (int i = 1; i < 8; i++) lm = fmaxf(lm, acc[i][j]);
        red[trow][tcol * 4 + j] = lm;
    }
    __syncthreads();
#pragma unroll
    for (int j = 0; j < 4; j++) {
        float mm = red[0][tcol * 4 + j];
#pragma unroll
        for (int r = 1; r < 8; r++) mm = fmaxf(mm, red[r][tcol * 4 + j]);
        m4[j] = mm;
    }
    __syncthreads();
    float ls[4] = {0.f, 0.f, 0.f, 0.f};
#pragma unroll
    for (int i = 0; i < 8; i++)
#pragma unroll
        for (int j = 0; j < 4; j++) {
            acc[i][j] = __expf(acc[i][j] - m4[j]);
            ls[j] += acc[i][j];
        }
#pragma unroll
    for (int j = 0; j < 4; j++) red[trow][tcol * 4 + j] = ls[j];
    __syncthreads();
#pragma unroll
    for (int j = 0; j < 4; j++) {
        float s = 0.f;
#pragma unroll
        for (int r = 0; r < 8; r++) s += red[r][tcol * 4 + j];
        ls[j] = 1.0f / s;
    }

    int qb = q0 + tcol * 4;
    if (qb < HW) {
#pragma unroll
        for (int i = 0; i < 8; i++) {
            int k = trow * 8 + i;
            unsigned short h[4], l[4];
#pragma unroll
            for (int j = 0; j < 4; j++) bsplit(acc[i][j] * ls[j], h[j], l[j]);
            size_t idx = ((size_t)n * KC + k) * HW + qb;
            *(ushort4*)&g_a_hi[idx] = make_ushort4(h[0], h[1], h[2], h[3]);
            *(ushort4*)&g_a_lo[idx] = make_ushort4(l[0], l[1], l[2], l[3]);
        }
    }
}

// ---------------------------------------------------------------------------
// Kernel B (mma.sync bf16): per (n,j): D[c,k] = sum_{q in 160} x[c,q]*a[k,q]
// hi/lo 3-pass. Output g_cwx (k,c); g_ca chunk a-sums.
// smem tiles row stride 168 bf16 (= 336B = 21*16B).
// ---------------------------------------------------------------------------
#define KB_RS   168
#define KB_XH   0
#define KB_XL   43008
#define KB_AH   86016
#define KB_AL   107520
#define KB_RED  129024
#define KB_SMEM (KB_RED + 4096)

__global__ __launch_bounds__(256, 1) void kB(const float* __restrict__ x) {
    extern __shared__ char smem[];
    const uint32_t sb = smem_u32(smem);
    const int tid = threadIdx.x;
    const int wid = tid >> 5;
    const int L   = tid & 31;
    const int n = blockIdx.x / NCH;
    const int j = blockIdx.x % NCH;

    unsigned short* sXH = (unsigned short*)(smem + KB_XH);
    unsigned short* sXL = (unsigned short*)(smem + KB_XL);
    unsigned short* sAH = (unsigned short*)(smem + KB_AH);
    unsigned short* sAL = (unsigned short*)(smem + KB_AL);
    float* redA = (float*)(smem + KB_RED);

    // ---- fill x tiles: 2048 (c,h) pairs ----
    const float* xb = x + (size_t)n * CD * HW + (size_t)j * 10;
#pragma unroll
    for (int it = 0; it < 8; ++it) {
        int p = tid + it * 256;
        int c = p >> 4, h = p & 15;
        const float* gp = xb + (size_t)c * HW + (size_t)h * WD;
        int colb = c * KB_RS + h * 10;
#pragma unroll
        for (int w2 = 0; w2 < 5; ++w2) {
            float2 v = *(const float2*)(gp + w2 * 2);
            unsigned short h0, l0, h1, l1;
            bsplit(v.x, h0, l0);
            bsplit(v.y, h1, l1);
            sXH[colb + w2 * 2]     = h0;
            sXH[colb + w2 * 2 + 1] = h1;
            sXL[colb + w2 * 2]     = l0;
            sXL[colb + w2 * 2 + 1] = l1;
        }
    }
    // ---- fill a tiles: 1024 (k,h) pairs; also a-sums ----
#pragma unroll
    for (int it = 0; it < 4; ++it) {
        int p = tid + it * 256;
        int k = p >> 4, h = p & 15;
        size_t gidx = ((size_t)n * KC + k) * HW + (size_t)h * WD + (size_t)j * 10;
        const unsigned short* gh = g_a_hi + gidx;
        const unsigned short* gl = g_a_lo + gidx;
        int colb = k * KB_RS + h * 10;
        float s = 0.f;
#pragma unroll
        for (int w = 0; w < 10; ++w) {
            unsigned short hh = gh[w], ll = gl[w];
            sAH[colb + w] = hh;
            sAL[colb + w] = ll;
            s += __bfloat162float(__ushort_as_bfloat16(hh)) +
                 __bfloat162float(__ushort_as_bfloat16(ll));
        }
        redA[h * 64 + k] = s;
    }
    __syncthreads();

    // a-sum reduction
    if (tid < 64) {
        float s = 0.f;
#pragma unroll
        for (int h = 0; h < 16; ++h) s += redA[h * 64 + tid];
        g_ca[((size_t)n * NCH + j) * KC + tid] = s;
    }

    // ---- mma: warp tile 32c x 32k ----
    const int wm = wid & 3;   // c block
    const int wn = wid >> 2;  // k block
    float acc[2][4][4];
#pragma unroll
    for (int mi = 0; mi < 2; mi++)
#pragma unroll
        for (int ni = 0; ni < 4; ni++)
#pragma unroll
            for (int e = 0; e < 4; e++) acc[mi][ni][e] = 0.f;

    const int a_row = (L & 7) + ((L >> 3) & 1) * 8;  // A frag lane row
    const int a_ch  = (L >> 4) * 8;                  // A frag col half
    const int b_row = (L & 7) + (L >> 4) * 8;        // B frag lane row (2 n-blocks)
    const int b_ch  = ((L >> 3) & 1) * 8;            // B frag col half

#pragma unroll
    for (int ks = 0; ks < 10; ++ks) {
        int kc = ks * 16;
        uint32_t axh[2][4], axl[2][4];
#pragma unroll
        for (int mi = 0; mi < 2; mi++) {
            uint32_t off = (uint32_t)((wm * 32 + mi * 16 + a_row) * KB_RS + kc + a_ch) * 2;
            ldm_x4(axh[mi], sb + KB_XH + off);
            ldm_x4(axl[mi], sb + KB_XL + off);
        }
        uint32_t bh[2][4], bl[2][4];
#pragma unroll
        for (int np = 0; np < 2; np++) {
            uint32_t off = (uint32_t)((wn * 32 + np * 16 + b_row) * KB_RS + kc + b_ch) * 2;
            ldm_x4(bh[np], sb + KB_AH + off);
            ldm_x4(bl[np], sb + KB_AL + off);
        }
#pragma unroll
        for (int mi = 0; mi < 2; mi++)
#pragma unroll
            for (int ni = 0; ni < 4; ni++) {
                uint32_t b0h = bh[ni >> 1][(ni & 1) * 2];
                uint32_t b1h = bh[ni >> 1][(ni & 1) * 2 + 1];
                uint32_t b0l = bl[ni >> 1][(ni & 1) * 2];
                uint32_t b1l = bl[ni >> 1][(ni & 1) * 2 + 1];
                mma16816(acc[mi][ni], axh[mi], b0h, b1h);
                mma16816(acc[mi][ni], axh[mi], b0l, b1l);
                mma16816(acc[mi][ni], axl[mi], b0h, b1h);
            }
    }
    __syncthreads();

    // ---- transpose D[c,k] -> T[k][c] in smem, then store (k,c) ----
    float* T = (float*)(smem + KB_XH);  // 64 x 132 floats
#pragma unroll
    for (int mi = 0; mi < 2; mi++)
#pragma unroll
        for (int ni = 0; ni < 4; ni++) {
            int c0 = wm * 32 + mi * 16 + (L >> 2);
            int kk = wn * 32 + ni * 8 + (L & 3) * 2;
            T[kk * 132 + c0]       = acc[mi][ni][0];
            T[(kk + 1) * 132 + c0] = acc[mi][ni][1];
            T[kk * 132 + c0 + 8]       = acc[mi][ni][2];
            T[(kk + 1) * 132 + c0 + 8] = acc[mi][ni][3];
        }
    __syncthreads();

    float* ob = g_cwx + (size_t)(n * NCH + j) * KC * CD;
    {
        int c4 = (tid & 31) * 4;
#pragma unroll
        for (int it = 0; it < 8; ++it) {
            int k = (tid >> 5) + it * 8;
            float4 v = *(float4*)&T[k * 132 + c4];
            *(float4*)&ob[(size_t)k * CD + c4] = v;
        }
    }
}

// ---------------------------------------------------------------------------
// Kernel C1: window assembly + residual + intra/global L2 norms
//            -> g_vh/g_vl bf16 hi/lo rows
// ---------------------------------------------------------------------------
__global__ __launch_bounds__(256) void kC1(const float* __restrict__ centers) {
    __shared__ float Asm[64];
    __shared__ float gred[8];

    const int wi   = blockIdx.x;
    const int n    = wi / NW;
    const int t    = wi % NW;
    const int tid  = threadIdx.x;
    const int tcol = tid & 31;
    const int trow = tid >> 5;

    if (tid < 64) {
        float s = 0.f;
#pragma unroll
        for (int i = 0; i < 20; i++) {
            int jj = (3 * t + i + 80) % NCH;
            s += g_ca[((size_t)n * NCH + jj) * KC + tid];
        }
        Asm[tid] = s;
    }
    __syncthreads();

    float acc[8][4];
#pragma unroll
    for (int i = 0; i < 8; i++)
#pragma unroll
        for (int jj = 0; jj < 4; jj++) acc[i][jj] = 0.f;

    for (int i = 0; i < 20; i++) {
        int jj = (3 * t + i + 80) % NCH;
        const float* base = g_cwx + (size_t)(n * NCH + jj) * KC * CD;
#pragma unroll
        for (int r = 0; r < 8; r++) {
            float4 v = *(const float4*)&base[(size_t)(trow * 8 + r) * CD + tcol * 4];
            acc[r][0] += v.x; acc[r][1] += v.y; acc[r][2] += v.z; acc[r][3] += v.w;
        }
    }

    float vv[8][4];
    float vsq = 0.f;
#pragma unroll
    for (int r = 0; r < 8; r++) {
        float As   = Asm[trow * 8 + r];
        float4 cen = *(const float4*)&centers[(size_t)(trow * 8 + r) * CD + tcol * 4];
        float r0 = acc[r][0] - cen.x * As;
        float r1 = acc[r][1] - cen.y * As;
        float r2 = acc[r][2] - cen.z * As;
        float r3 = acc[r][3] - cen.w * As;
        float ns = r0 * r0 + r1 * r1 + r2 * r2 + r3 * r3;
#pragma unroll
        for (int off = 16; off > 0; off >>= 1)
            ns += __shfl_xor_sync(0xffffffffu, ns, off);
        float inv = 1.0f / fmaxf(sqrtf(ns), 1e-12f);
        vv[r][0] = r0 * inv; vv[r][1] = r1 * inv;
        vv[r][2] = r2 * inv; vv[r][3] = r3 * inv;
        vsq += vv[r][0] * vv[r][0] + vv[r][1] * vv[r][1] +
               vv[r][2] * vv[r][2] + vv[r][3] * vv[r][3];
    }
#pragma unroll
    for (int off = 16; off > 0; off >>= 1)
        vsq += __shfl_xor_sync(0xffffffffu, vsq, off);
    if (tcol == 0) gred[trow] = vsq;
    __syncthreads();
    float g = 0.f;
#pragma unroll
    for (int r = 0; r < 8; r++) g += gred[r];
    float ginv = 1.0f / fmaxf(sqrtf(g), 1e-12f);

#pragma unroll
    for (int r = 0; r < 8; r++) {
        unsigned short h[4], l[4];
#pragma unroll
        for (int e = 0; e < 4; e++) bsplit(vv[r][e] * ginv, h[e], l[e]);
        size_t idx = (size_t)wi * KD + (size_t)(trow * 8 + r) * CD + tcol * 4;
        *(ushort4*)&g_vh[idx] = make_ushort4(h[0], h[1], h[2], h[3]);
        *(ushort4*)&g_vl[idx] = make_ushort4(l[0], l[1], l[2], l[3]);
    }
}

// ---------------------------------------------------------------------------
// Kernel C2 (mma.sync bf16): split-K partials of (256x8192)@(8192x256)
// BM=128, BN=64, K-chunk 512, grid (2,4,16). Warp tile 64m x 16n.
// smem stage: 64 k at a time, row stride 72 bf16.
// ---------------------------------------------------------------------------
#define C2_RS  72
#define C2_AH  0
#define C2_AL  18432
#define C2_BH  36864
#define C2_BL  46080
#define C2_SMEM 55296

__global__ __launch_bounds__(256, 2) void kC2() {
    extern __shared__ char smem[];
    const uint32_t sb = smem_u32(smem);
    const int tid = threadIdx.x;
    const int wid = tid >> 5;
    const int L   = tid & 31;
    const int m0  = blockIdx.x * 128;
    const int n0  = blockIdx.y * 64;
    const int k0  = blockIdx.z * 512;

    unsigned short* sAH = (unsigned short*)(smem + C2_AH);
    unsigned short* sAL = (unsigned short*)(smem + C2_AL);
    unsigned short* sBH = (unsigned short*)(smem + C2_BH);
    unsigned short* sBL = (unsigned short*)(smem + C2_BL);

    const int wm = wid & 1;   // m block of 64
    const int wn = wid >> 1;  // n block of 16

    float acc[4][2][4];
#pragma unroll
    for (int mi = 0; mi < 4; mi++)
#pragma unroll
        for (int ni = 0; ni < 2; ni++)
#pragma unroll
            for (int e = 0; e < 4; e++) acc[mi][ni][e] = 0.f;

    const int a_row = (L & 7) + ((L >> 3) & 1) * 8;
    const int a_ch  = (L >> 4) * 8;
    const int b_row = (L & 7) + (L >> 4) * 8;
    const int b_ch  = ((L >> 3) & 1) * 8;

    for (int stage = 0; stage < 8; ++stage) {
        int kb = k0 + stage * 64;
        // stage A: 128 rows x 64 k (hi+lo), 4+4 uint4 per thread
#pragma unroll
        for (int it = 0; it < 4; ++it) {
            int p = tid + it * 256;
            int row = p >> 3, cg = (p & 7) * 8;
            size_t g = (size_t)(m0 + row) * KD + kb + cg;
            *(uint4*)&sAH[row * C2_RS + cg] = *(const uint4*)&g_vh[g];
            *(uint4*)&sAL[row * C2_RS + cg] = *(const uint4*)&g_vl[g];
        }
        // stage B: 64 rows x 64 k
#pragma unroll
        for (int it = 0; it < 2; ++it) {
            int p = tid + it * 256;
            int row = p >> 3, cg = (p & 7) * 8;
            size_t g = (size_t)(n0 + row) * KD + kb + cg;
            *(uint4*)&sBH[row * C2_RS + cg] = *(const uint4*)&g_wh[g];
            *(uint4*)&sBL[row * C2_RS + cg] = *(const uint4*)&g_wl[g];
        }
        __syncthreads();

#pragma unroll
        for (int ks = 0; ks < 4; ++ks) {
            int kc = ks * 16;
            uint32_t bhf[4], blf[4];
            {
                uint32_t off = (uint32_t)((wn * 16 + b_row) * C2_RS + kc + b_ch) * 2;
                ldm_x4(bhf, sb + C2_BH + off);
                ldm_x4(blf, sb + C2_BL + off);
            }
#pragma unroll
            for (int mi = 0; mi < 4; mi++) {
                uint32_t ah[4], al[4];
                uint32_t off = (uint32_t)((wm * 64 + mi * 16 + a_row) * C2_RS + kc + a_ch) * 2;
                ldm_x4(ah, sb + C2_AH + off);
                ldm_x4(al, sb + C2_AL + off);
#pragma unroll
                for (int ni = 0; ni < 2; ni++) {
                    mma16816(acc[mi][ni], ah, bhf[ni * 2], bhf[ni * 2 + 1]);
                    mma16816(acc[mi][ni], ah, blf[ni * 2], blf[ni * 2 + 1]);
                    mma16816(acc[mi][ni], al, bhf[ni * 2], bhf[ni * 2 + 1]);
                }
            }
        }
        __syncthreads();
    }

    float* pb = g_part + (size_t)blockIdx.z * NR * OD;
#pragma unroll
    for (int mi = 0; mi < 4; mi++) {
        int m_lo = m0 + wm * 64 + mi * 16 + (L >> 2);
        int nn   = n0 + wn * 16 + (L & 3) * 2;
#pragma unroll
        for (int ni = 0; ni < 2; ni++) {
            int nc = nn + ni * 8;
            if (m_lo < NR)
                *(float2*)&pb[(size_t)m_lo * OD + nc] =
                    make_float2(acc[mi][ni][0], acc[mi][ni][1]);
            if (m_lo + 8 < NR)
                *(float2*)&pb[(size_t)(m_lo + 8) * OD + nc] =
                    make_float2(acc[mi][ni][2], acc[mi][ni][3]);
        }
    }
}

// ---------------------------------------------------------------------------
// Kernel C3: reduce split-K partials + bias + final row L2 norm -> output
// ---------------------------------------------------------------------------
__global__ __launch_bounds__(256) void kC3(const float* __restrict__ mb,
                                           float* __restrict__ out) {
    __shared__ float red[8];
    const int rrow = blockIdx.x;
    const int tid  = threadIdx.x;
    float s = mb[tid];
#pragma unroll
    for (int ks = 0; ks < KSP; ks++)
        s += g_part[((size_t)ks * NR + rrow) * OD + tid];
    float sq = s * s;
#pragma unroll
    for (int off = 16; off > 0; off >>= 1)
        sq += __shfl_xor_sync(0xffffffffu, sq, off);
    if ((tid & 31) == 0) red[tid >> 5] = sq;
    __syncthreads();
    float tot = 0.f;
#pragma unroll
    for (int i = 0; i < 8; i++) tot += red[i];
    out[(size_t)rrow * OD + tid] = s / fmaxf(sqrtf(tot), 1e-12f);
}

extern "C" void kernel_launch(void* const* d_in, const int* in_sizes, int n_in,
                              void* d_out, int out_size) {
    (void)in_sizes; (void)n_in; (void)out_size;
    const float* x       = (const float*)d_in[0];
    const float* centers = (const float*)d_in[1];
    const float* cw      = (const float*)d_in[2];
    const float* cb      = (const float*)d_in[3];
    const float* mw      = (const float*)d_in[4];
    const float* mb      = (const float*)d_in[5];
    float* out = (float*)d_out;

    static int inited = 0;
    if (!inited) {
        cudaFuncSetAttribute(kB, cudaFuncAttributeMaxDynamicSharedMemorySize, KB_SMEM);
        cudaFuncSetAttribute(kC2, cudaFuncAttributeMaxDynamicSharedMemorySize, C2_SMEM);
        inited = 1;
    }

    kW<<<OD * KD / (256 * 8), 256>>>(mw);
    kA<<<NB * 113, 256>>>(x, cw, cb);
    kB<<<NB * NCH, 256, KB_SMEM>>>(x);
    kC1<<<NR, 256>>>(centers);
    kC2<<<dim3(2, 4, KSP), 256, C2_SMEM>>>();
    kC3<<<NR, 256>>>(mb, out);
}

// round 4
// speedup vs baseline: 1.4646x; 1.1957x over previous
#include <cuda_runtime.h>
#include <cuda_bf16.h>
#include <math.h>
#include <stdint.h>

#define NB 8
#define CD 128
#define KC 64
#define HD 16
#define WD 900
#define HW 14400
#define NCH 90
#define NW 30
#define NR 240
#define NRP 256
#define OD 256
#define KSP 16
#define KD 8192

__device__ unsigned short g_a_hi[(size_t)NB * KC * HW];   // bf16 bits, (n,k,q)
__device__ unsigned short g_a_lo[(size_t)NB * KC * HW];
__device__ float g_cwx[(size_t)NB * NCH * KC * CD];       // (n,j,k,c)
__device__ float g_ca[(size_t)NB * NCH * KC];             // (n,j,k)
__device__ unsigned short g_vh[(size_t)NRP * KD];         // vlad bf16 hi (rows>=240 stay 0)
__device__ unsigned short g_vl[(size_t)NRP * KD];
__device__ unsigned short g_wh[(size_t)OD * KD];
__device__ unsigned short g_wl[(size_t)OD * KD];
__device__ float g_part[(size_t)KSP * NR * OD];

// ---------------------------------------------------------------------------
// helpers
// ---------------------------------------------------------------------------
__device__ __forceinline__ uint32_t smem_u32(const void* p) {
    uint32_t a;
    asm("{ .reg .u64 t; cvta.to.shared.u64 t, %1; cvt.u32.u64 %0, t; }"
        : "=r"(a) : "l"(p));
    return a;
}
__device__ __forceinline__ void ldm_x4(uint32_t (&r)[4], uint32_t addr) {
    asm volatile("ldmatrix.sync.aligned.m8n8.x4.shared.b16 {%0,%1,%2,%3}, [%4];"
                 : "=r"(r[0]), "=r"(r[1]), "=r"(r[2]), "=r"(r[3]) : "r"(addr));
}
__device__ __forceinline__ void mma16816(float (&d)[4], const uint32_t (&a)[4],
                                         const uint32_t b0, const uint32_t b1) {
    asm volatile(
        "mma.sync.aligned.m16n8k16.row.col.f32.bf16.bf16.f32 "
        "{%0,%1,%2,%3}, {%4,%5,%6,%7}, {%8,%9}, {%0,%1,%2,%3};"
        : "+f"(d[0]), "+f"(d[1]), "+f"(d[2]), "+f"(d[3])
        : "r"(a[0]), "r"(a[1]), "r"(a[2]), "r"(a[3]), "r"(b0), "r"(b1));
}
__device__ __forceinline__ void bsplit(float v, unsigned short& h, unsigned short& l) {
    __nv_bfloat16 bh = __float2bfloat16(v);
    __nv_bfloat16 bl = __float2bfloat16(v - __bfloat162float(bh));
    h = __bfloat16_as_ushort(bh);
    l = __bfloat16_as_ushort(bl);
}
__device__ __forceinline__ float bf(unsigned short u) {
    return __bfloat162float(__ushort_as_bfloat16(u));
}

// ---------------------------------------------------------------------------
// Kernel W: convert mlp_w to bf16 hi/lo
// ---------------------------------------------------------------------------
__global__ __launch_bounds__(256) void kW(const float* __restrict__ mw) {
    size_t base = ((size_t)blockIdx.x * 256 + threadIdx.x) * 8;
    float4 v0 = *(const float4*)(mw + base);
    float4 v1 = *(const float4*)(mw + base + 4);
    float vv[8] = {v0.x, v0.y, v0.z, v0.w, v1.x, v1.y, v1.z, v1.w};
    unsigned short h[8], l[8];
#pragma unroll
    for (int i = 0; i < 8; i++) bsplit(vv[i], h[i], l[i]);
    *(ushort4*)(g_wh + base)     = make_ushort4(h[0], h[1], h[2], h[3]);
    *(ushort4*)(g_wh + base + 4) = make_ushort4(h[4], h[5], h[6], h[7]);
    *(ushort4*)(g_wl + base)     = make_ushort4(l[0], l[1], l[2], l[3]);
    *(ushort4*)(g_wl + base + 4) = make_ushort4(l[4], l[5], l[6], l[7]);
}

// ---------------------------------------------------------------------------
// Kernel A (mma.sync): logits D[q,k] = sum_c x[c,q] w[k,c]; softmax over k in
// fragments; output a as bf16 hi/lo, layout (n,k,q).
// ---------------------------------------------------------------------------
#define A_RS   136
#define A_XH   0
#define A_XL   (A_XH + 128 * A_RS * 2)   // 34816
#define A_WH   (A_XL + 128 * A_RS * 2)   // 69632
#define A_WL   (A_WH + 64 * A_RS * 2)    // 87040
#define A_CB   (A_WL + 64 * A_RS * 2)    // 104448
#define A_SMEM (A_CB + 256)

__global__ __launch_bounds__(256, 1) void kA(const float* __restrict__ x,
                                             const float* __restrict__ cw,
                                             const float* __restrict__ cb) {
    extern __shared__ char smem[];
    const uint32_t sb = smem_u32(smem);
    unsigned short* sXH = (unsigned short*)(smem + A_XH);
    unsigned short* sXL = (unsigned short*)(smem + A_XL);
    unsigned short* sWH = (unsigned short*)(smem + A_WH);
    unsigned short* sWL = (unsigned short*)(smem + A_WL);
    float* cbs = (float*)(smem + A_CB);

    const int tid = threadIdx.x;
    const int wid = tid >> 5;
    const int L   = tid & 31;
    const int n   = blockIdx.x / 113;
    const int q0  = (blockIdx.x % 113) * 128;
    const int vq  = (HW - q0 < 128) ? (HW - q0) : 128;

    // stage W[k][c] hi/lo (contiguous ushort4 stores)
    {
        int k = tid >> 2, cg = (tid & 3) * 32;
        const float* wp = cw + k * CD + cg;
#pragma unroll
        for (int it = 0; it < 8; ++it) {
            float4 v = *(const float4*)(wp + it * 4);
            unsigned short h[4], l[4];
            bsplit(v.x, h[0], l[0]); bsplit(v.y, h[1], l[1]);
            bsplit(v.z, h[2], l[2]); bsplit(v.w, h[3], l[3]);
            *(ushort4*)&sWH[k * A_RS + cg + it * 4] = make_ushort4(h[0], h[1], h[2], h[3]);
            *(ushort4*)&sWL[k * A_RS + cg + it * 4] = make_ushort4(l[0], l[1], l[2], l[3]);
        }
    }
    if (tid < 64) cbs[tid] = cb[tid];

    // stage X^T: sX[q][c] hi/lo (scattered 2B stores)
    {
        int c = tid >> 1, qh = (tid & 1) * 64;
        const float* xp = x + (size_t)n * CD * HW + (size_t)c * HW + q0 + qh;
#pragma unroll
        for (int it = 0; it < 16; ++it) {
            int qq = qh + it * 4;
            float4 v = (qq < vq) ? *(const float4*)(xp + it * 4)
                                 : make_float4(0.f, 0.f, 0.f, 0.f);
            float vv[4] = {v.x, v.y, v.z, v.w};
#pragma unroll
            for (int e = 0; e < 4; ++e) {
                unsigned short h, l;
                bsplit(vv[e], h, l);
                sXH[(qq + e) * A_RS + c] = h;
                sXL[(qq + e) * A_RS + c] = l;
            }
        }
    }
    __syncthreads();

    const int a_row = (L & 7) + ((L >> 3) & 1) * 8;
    const int a_ch  = (L >> 4) * 8;
    const int b_row = (L & 7) + (L >> 4) * 8;
    const int b_ch  = ((L >> 3) & 1) * 8;

    float acc[8][4];
#pragma unroll
    for (int ni = 0; ni < 8; ni++)
#pragma unroll
        for (int e = 0; e < 4; e++) acc[ni][e] = 0.f;

#pragma unroll
    for (int kc = 0; kc < 128; kc += 16) {
        uint32_t axh[4], axl[4];
        uint32_t offa = (uint32_t)((wid * 16 + a_row) * A_RS + kc + a_ch) * 2;
        ldm_x4(axh, sb + A_XH + offa);
        ldm_x4(axl, sb + A_XL + offa);
        uint32_t bh[4][4], bl[4][4];
#pragma unroll
        for (int nb = 0; nb < 4; ++nb) {
            uint32_t offb = (uint32_t)((nb * 16 + b_row) * A_RS + kc + b_ch) * 2;
            ldm_x4(bh[nb], sb + A_WH + offb);
            ldm_x4(bl[nb], sb + A_WL + offb);
        }
#pragma unroll
        for (int ni = 0; ni < 8; ++ni) {
            uint32_t b0h = bh[ni >> 1][(ni & 1) * 2];
            uint32_t b1h = bh[ni >> 1][(ni & 1) * 2 + 1];
            uint32_t b0l = bl[ni >> 1][(ni & 1) * 2];
            uint32_t b1l = bl[ni >> 1][(ni & 1) * 2 + 1];
            mma16816(acc[ni], axh, b0h, b1h);
            mma16816(acc[ni], axh, b0l, b1l);
            mma16816(acc[ni], axl, b0h, b1h);
        }
    }

    // bias + softmax over k (64 values per q-row spread over a lane quad)
    float m0 = -1e30f, m1 = -1e30f;
#pragma unroll
    for (int ni = 0; ni < 8; ++ni) {
        int k0 = ni * 8 + (L & 3) * 2;
        float b0 = cbs[k0], b1 = cbs[k0 + 1];
        acc[ni][0] += b0; acc[ni][1] += b1;
        acc[ni][2] += b0; acc[ni][3] += b1;
        m0 = fmaxf(m0, fmaxf(acc[ni][0], acc[ni][1]));
        m1 = fmaxf(m1, fmaxf(acc[ni][2], acc[ni][3]));
    }
    m0 = fmaxf(m0, __shfl_xor_sync(0xffffffffu, m0, 1));
    m0 = fmaxf(m0, __shfl_xor_sync(0xffffffffu, m0, 2));
    m1 = fmaxf(m1, __shfl_xor_sync(0xffffffffu, m1, 1));
    m1 = fmaxf(m1, __shfl_xor_sync(0xffffffffu, m1, 2));
    float s0 = 0.f, s1 = 0.f;
#pragma unroll
    for (int ni = 0; ni < 8; ++ni) {
        acc[ni][0] = __expf(acc[ni][0] - m0);
        acc[ni][1] = __expf(acc[ni][1] - m0);
        acc[ni][2] = __expf(acc[ni][2] - m1);
        acc[ni][3] = __expf(acc[ni][3] - m1);
        s0 += acc[ni][0] + acc[ni][1];
        s1 += acc[ni][2] + acc[ni][3];
    }
    s0 += __shfl_xor_sync(0xffffffffu, s0, 1);
    s0 += __shfl_xor_sync(0xffffffffu, s0, 2);
    s1 += __shfl_xor_sync(0xffffffffu, s1, 1);
    s1 += __shfl_xor_sync(0xffffffffu, s1, 2);
    float i0 = 1.0f / s0, i1 = 1.0f / s1;

    __syncthreads();   // reuse sXH/sXL as a-tile [k][q]
    unsigned short* sAH = sXH;
    unsigned short* sAL = sXL;
    {
        int qr0 = wid * 16 + (L >> 2);
        int qr1 = qr0 + 8;
#pragma unroll
        for (int ni = 0; ni < 8; ++ni) {
            int k0 = ni * 8 + (L & 3) * 2;
            unsigned short h, l;
            bsplit(acc[ni][0] * i0, h, l);
            sAH[k0 * A_RS + qr0] = h;       sAL[k0 * A_RS + qr0] = l;
            bsplit(acc[ni][1] * i0, h, l);
            sAH[(k0 + 1) * A_RS + qr0] = h; sAL[(k0 + 1) * A_RS + qr0] = l;
            bsplit(acc[ni][2] * i1, h, l);
            sAH[k0 * A_RS + qr1] = h;       sAL[k0 * A_RS + qr1] = l;
            bsplit(acc[ni][3] * i1, h, l);
            sAH[(k0 + 1) * A_RS + qr1] = h; sAL[(k0 + 1) * A_RS + qr1] = l;
        }
    }
    __syncthreads();

    // coalesced copy out
#pragma unroll
    for (int it = 0; it < 4; ++it) {
        int e = tid + it * 256;
        int k = e >> 4, qg = (e & 15) * 8;
        if (qg < vq) {
            size_t g = ((size_t)n * KC + k) * HW + q0 + qg;
            *(uint4*)&g_a_hi[g] = *(uint4*)&sAH[k * A_RS + qg];
            *(uint4*)&g_a_lo[g] = *(uint4*)&sAL[k * A_RS + qg];
        }
    }
}

// ---------------------------------------------------------------------------
// Kernel B (mma.sync): per (n,j): D[k,c] = sum_{q in 160} a[k,q] x[c,q]
// M=k(64), N=c(128), K=q. Two K-stages of 80. Direct (k,c) store.
// ---------------------------------------------------------------------------
#define B_RS   88
#define B_AH   0
#define B_AL   11264
#define B_XH   22528
#define B_XL   45056
#define B_RED  67584
#define B_SMEM (B_RED + 4096)

__global__ __launch_bounds__(256, 2) void kB(const float* __restrict__ x) {
    extern __shared__ char smem[];
    const uint32_t sb = smem_u32(smem);
    unsigned short* sAH = (unsigned short*)(smem + B_AH);
    unsigned short* sAL = (unsigned short*)(smem + B_AL);
    unsigned short* sXH = (unsigned short*)(smem + B_XH);
    unsigned short* sXL = (unsigned short*)(smem + B_XL);
    float* redA = (float*)(smem + B_RED);

    const int tid = threadIdx.x;
    const int wid = tid >> 5;
    const int L   = tid & 31;
    const int n = blockIdx.x / NCH;
    const int j = blockIdx.x % NCH;

    const int wk = wid & 3;    // k block of 16
    const int wc = wid >> 2;   // c block of 64

    const int a_row = (L & 7) + ((L >> 3) & 1) * 8;
    const int a_ch  = (L >> 4) * 8;
    const int b_row = (L & 7) + (L >> 4) * 8;
    const int b_ch  = ((L >> 3) & 1) * 8;

    float acc[8][4];
#pragma unroll
    for (int ni = 0; ni < 8; ni++)
#pragma unroll
        for (int e = 0; e < 4; e++) acc[ni][e] = 0.f;

#pragma unroll
    for (int s = 0; s < 2; ++s) {
        // stage a tiles: (k, h8) pairs, 512 per stage
#pragma unroll
        for (int it = 0; it < 2; ++it) {
            int p = tid + it * 256;
            int k = p >> 3, h8 = p & 7;
            int h = s * 8 + h8;
            size_t gidx = ((size_t)n * KC + k) * HW + (size_t)h * WD + (size_t)j * 10;
            const uint* gh = (const uint*)(g_a_hi + gidx);
            const uint* gl = (const uint*)(g_a_lo + gidx);
            int colb = k * B_RS + h8 * 10;
            float sum = 0.f;
#pragma unroll
            for (int w2 = 0; w2 < 5; ++w2) {
                uint vh = gh[w2], vl = gl[w2];
                *(uint*)&sAH[colb + w2 * 2] = vh;
                *(uint*)&sAL[colb + w2 * 2] = vl;
                sum += bf((unsigned short)(vh & 0xffff)) + bf((unsigned short)(vh >> 16)) +
                       bf((unsigned short)(vl & 0xffff)) + bf((unsigned short)(vl >> 16));
            }
            redA[h * 64 + k] = sum;
        }
        // stage x tiles: (c, h8) pairs, 1024 per stage
#pragma unroll
        for (int it = 0; it < 4; ++it) {
            int p = tid + it * 256;
            int c = p >> 3, h8 = p & 7;
            int h = s * 8 + h8;
            const float* gp = x + (size_t)n * CD * HW + (size_t)c * HW +
                              (size_t)h * WD + (size_t)j * 10;
            int colb = c * B_RS + h8 * 10;
#pragma unroll
            for (int w2 = 0; w2 < 5; ++w2) {
                float2 v = *(const float2*)(gp + w2 * 2);
                unsigned short h0, l0, h1, l1;
                bsplit(v.x, h0, l0);
                bsplit(v.y, h1, l1);
                *(uint*)&sXH[colb + w2 * 2] = (uint)h0 | ((uint)h1 << 16);
                *(uint*)&sXL[colb + w2 * 2] = (uint)l0 | ((uint)l1 << 16);
            }
        }
        __syncthreads();

#pragma unroll
        for (int ks = 0; ks < 5; ++ks) {
            int kc = ks * 16;
            uint32_t ah[4], al[4];
            uint32_t offa = (uint32_t)((wk * 16 + a_row) * B_RS + kc + a_ch) * 2;
            ldm_x4(ah, sb + B_AH + offa);
            ldm_x4(al, sb + B_AL + offa);
            uint32_t bh[4][4], bl[4][4];
#pragma unroll
            for (int nb = 0; nb < 4; ++nb) {
                uint32_t offb = (uint32_t)((wc * 64 + nb * 16 + b_row) * B_RS + kc + b_ch) * 2;
                ldm_x4(bh[nb], sb + B_XH + offb);
                ldm_x4(bl[nb], sb + B_XL + offb);
            }
#pragma unroll
            for (int ni = 0; ni < 8; ++ni) {
                uint32_t b0h = bh[ni >> 1][(ni & 1) * 2];
                uint32_t b1h = bh[ni >> 1][(ni & 1) * 2 + 1];
                uint32_t b0l = bl[ni >> 1][(ni & 1) * 2];
                uint32_t b1l = bl[ni >> 1][(ni & 1) * 2 + 1];
                mma16816(acc[ni], ah, b0h, b1h);
                mma16816(acc[ni], ah, b0l, b1l);
                mma16816(acc[ni], al, b0h, b1h);
            }
        }
        __syncthreads();
    }

    // chunk a-sums
    if (tid < 64) {
        float sum = 0.f;
#pragma unroll
        for (int h = 0; h < 16; ++h) sum += redA[h * 64 + tid];
        g_ca[((size_t)n * NCH + j) * KC + tid] = sum;
    }

    // direct (k,c) store
    float* ob = g_cwx + (size_t)(n * NCH + j) * KC * CD;
    int k0 = wk * 16 + (L >> 2);
    int cb0 = wc * 64 + (L & 3) * 2;
#pragma unroll
    for (int ni = 0; ni < 8; ++ni) {
        int c = cb0 + ni * 8;
        *(float2*)&ob[(size_t)k0 * CD + c]       = make_float2(acc[ni][0], acc[ni][1]);
        *(float2*)&ob[(size_t)(k0 + 8) * CD + c] = make_float2(acc[ni][2], acc[ni][3]);
    }
}

// ---------------------------------------------------------------------------
// Kernel C1: window assembly + residual + intra-norm; global norm = 1/8 exact
// (64 unit sub-vectors). Warp-per-k, 8 k per block, grid (240, 8). No smem.
// ---------------------------------------------------------------------------
__global__ __launch_bounds__(256) void kC1(const float* __restrict__ centers) {
    const int wi  = blockIdx.x;
    const int n   = wi / NW;
    const int t   = wi % NW;
    const int tid = threadIdx.x;
    const int L   = tid & 31;
    const int k   = blockIdx.y * 8 + (tid >> 5);
    const int c4  = L * 4;

    // window a-sum for this k
    float As = 0.f;
    if (L < 20) {
        int jj = (3 * t + L + 80) % NCH;
        As = g_ca[((size_t)n * NCH + jj) * KC + k];
    }
#pragma unroll
    for (int off = 16; off > 0; off >>= 1)
        As += __shfl_xor_sync(0xffffffffu, As, off);

    float a0 = 0.f, a1 = 0.f, a2 = 0.f, a3 = 0.f;
#pragma unroll 5
    for (int i = 0; i < 20; ++i) {
        int jj = (3 * t + i + 80) % NCH;
        const float4 v = *(const float4*)&g_cwx[(((size_t)n * NCH + jj) * KC + k) * CD + c4];
        a0 += v.x; a1 += v.y; a2 += v.z; a3 += v.w;
    }
    float4 cen = *(const float4*)&centers[(size_t)k * CD + c4];
    float r0 = a0 - cen.x * As;
    float r1 = a1 - cen.y * As;
    float r2 = a2 - cen.z * As;
    float r3 = a3 - cen.w * As;
    float ns = r0 * r0 + r1 * r1 + r2 * r2 + r3 * r3;
#pragma unroll
    for (int off = 16; off > 0; off >>= 1)
        ns += __shfl_xor_sync(0xffffffffu, ns, off);
    float inv = 0.125f / fmaxf(sqrtf(ns), 1e-12f);

    unsigned short h[4], l[4];
    bsplit(r0 * inv, h[0], l[0]);
    bsplit(r1 * inv, h[1], l[1]);
    bsplit(r2 * inv, h[2], l[2]);
    bsplit(r3 * inv, h[3], l[3]);
    size_t idx = (size_t)wi * KD + (size_t)k * CD + c4;
    *(ushort4*)&g_vh[idx] = make_ushort4(h[0], h[1], h[2], h[3]);
    *(ushort4*)&g_vl[idx] = make_ushort4(l[0], l[1], l[2], l[3]);
}

// ---------------------------------------------------------------------------
// Kernel C2 (mma.sync bf16): split-K partials of (256x8192)@(8192x256)
// ---------------------------------------------------------------------------
#define C2_RS  72
#define C2_AH  0
#define C2_AL  18432
#define C2_BH  36864
#define C2_BL  46080
#define C2_SMEM 55296

__global__ __launch_bounds__(256, 2) void kC2() {
    extern __shared__ char smem[];
    const uint32_t sb = smem_u32(smem);
    const int tid = threadIdx.x;
    const int wid = tid >> 5;
    const int L   = tid & 31;
    const int m0  = blockIdx.x * 128;
    const int n0  = blockIdx.y * 64;
    const int k0  = blockIdx.z * 512;

    unsigned short* sAH = (unsigned short*)(smem + C2_AH);
    unsigned short* sAL = (unsigned short*)(smem + C2_AL);
    unsigned short* sBH = (unsigned short*)(smem + C2_BH);
    unsigned short* sBL = (unsigned short*)(smem + C2_BL);

    const int wm = wid & 1;
    const int wn = wid >> 1;

    float acc[4][2][4];
#pragma unroll
    for (int mi = 0; mi < 4; mi++)
#pragma unroll
        for (int ni = 0; ni < 2; ni++)
#pragma unroll
            for (int e = 0; e < 4; e++) acc[mi][ni][e] = 0.f;

    const int a_row = (L & 7) + ((L >> 3) & 1) * 8;
    const int a_ch  = (L >> 4) * 8;
    const int b_row = (L & 7) + (L >> 4) * 8;
    const int b_ch  = ((L >> 3) & 1) * 8;

    for (int stage = 0; stage < 8; ++stage) {
        int kb = k0 + stage * 64;
#pragma unroll
        for (int it = 0; it < 4; ++it) {
            int p = tid + it * 256;
            int row = p >> 3, cg = (p & 7) * 8;
            size_t g = (size_t)(m0 + row) * KD + kb + cg;
            *(uint4*)&sAH[row * C2_RS + cg] = *(const uint4*)&g_vh[g];
            *(uint4*)&sAL[row * C2_RS + cg] = *(const uint4*)&g_vl[g];
        }
#pragma unroll
        for (int it = 0; it < 2; ++it) {
            int p = tid + it * 256;
            int row = p >> 3, cg = (p & 7) * 8;
            size_t g = (size_t)(n0 + row) * KD + kb + cg;
            *(uint4*)&sBH[row * C2_RS + cg] = *(const uint4*)&g_wh[g];
            *(uint4*)&sBL[row * C2_RS + cg] = *(const uint4*)&g_wl[g];
        }
        __syncthreads();

#pragma unroll
        for (int ks = 0; ks < 4; ++ks) {
            int kc = ks * 16;
            uint32_t bhf[4], blf[4];
            {
                uint32_t off = (uint32_t)((wn * 16 + b_row) * C2_RS + kc + b_ch) * 2;
                ldm_x4(bhf, sb + C2_BH + off);
                ldm_x4(blf, sb + C2_BL + off);
            }
#pragma unroll
            for (int mi = 0; mi < 4; mi++) {
                uint32_t ah[4], al[4];
                uint32_t off = (uint32_t)((wm * 64 + mi * 16 + a_row) * C2_RS + kc + a_ch) * 2;
                ldm_x4(ah, sb + C2_AH + off);
                ldm_x4(al, sb + C2_AL + off);
#pragma unroll
                for (int ni = 0; ni < 2; ni++) {
                    mma16816(acc[mi][ni], ah, bhf[ni * 2], bhf[ni * 2 + 1]);
                    mma16816(acc[mi][ni], ah, blf[ni * 2], blf[ni * 2 + 1]);
                    mma16816(acc[mi][ni], al, bhf[ni * 2], bhf[ni * 2 + 1]);
                }
            }
        }
        __syncthreads();
    }

    float* pb = g_part + (size_t)blockIdx.z * NR * OD;
#pragma unroll
    for (int mi = 0; mi < 4; mi++) {
        int m_lo = m0 + wm * 64 + mi * 16 + (L >> 2);
        int nn   = n0 + wn * 16 + (L & 3) * 2;
#pragma unroll
        for (int ni = 0; ni < 2; ni++) {
            int nc = nn + ni * 8;
            if (m_lo < NR)
                *(float2*)&pb[(size_t)m_lo * OD + nc] =
                    make_float2(acc[mi][ni][0], acc[mi][ni][1]);
            if (m_lo + 8 < NR)
                *(float2*)&pb[(size_t)(m_lo + 8) * OD + nc] =
                    make_float2(acc[mi][ni][2], acc[mi][ni][3]);
        }
    }
}

// ---------------------------------------------------------------------------
// Kernel C3: reduce split-K partials + bias + final row L2 norm -> output
// ---------------------------------------------------------------------------
__global__ __launch_bounds__(256) void kC3(const float* __restrict__ mb,
                                           float* __restrict__ out) {
    __shared__ float red[8];
    const int rrow = blockIdx.x;
    const int tid  = threadIdx.x;
    float s = mb[tid];
#pragma unroll
    for (int ks = 0; ks < KSP; ks++)
        s += g_part[((size_t)ks * NR + rrow) * OD + tid];
    float sq = s * s;
#pragma unroll
    for (int off = 16; off > 0; off >>= 1)
        sq += __shfl_xor_sync(0xffffffffu, sq, off);
    if ((tid & 31) == 0) red[tid >> 5] = sq;
    __syncthreads();
    float tot = 0.f;
#pragma unroll
    for (int i = 0; i < 8; i++) tot += red[i];
    out[(size_t)rrow * OD + tid] = s / fmaxf(sqrtf(tot), 1e-12f);
}

extern "C" void kernel_launch(void* const* d_in, const int* in_sizes, int n_in,
                              void* d_out, int out_size) {
    (void)in_sizes; (void)n_in; (void)out_size;
    const float* x       = (const float*)d_in[0];
    const float* centers = (const float*)d_in[1];
    const float* cw      = (const float*)d_in[2];
    const float* cb      = (const float*)d_in[3];
    const float* mw      = (const float*)d_in[4];
    const float* mb      = (const float*)d_in[5];
    float* out = (float*)d_out;

    cudaFuncSetAttribute(kA, cudaFuncAttributeMaxDynamicSharedMemorySize, A_SMEM);
    cudaFuncSetAttribute(kB, cudaFuncAttributeMaxDynamicSharedMemorySize, B_SMEM);
    cudaFuncSetAttribute(kC2, cudaFuncAttributeMaxDynamicSharedMemorySize, C2_SMEM);

    kW<<<OD * KD / (256 * 8), 256>>>(mw);
    kA<<<NB * 113, 256, A_SMEM>>>(x, cw, cb);
    kB<<<NB * NCH, 256, B_SMEM>>>(x);
    kC1<<<dim3(NR, 8), 256>>>(centers);
    kC2<<<dim3(2, 4, KSP), 256, C2_SMEM>>>();
    kC3<<<NR, 256>>>(mb, out);
}